// round 16
// baseline (speedup 1.0000x reference)
#include <cuda_runtime.h>
#include <cuda_fp16.h>
#include <cstdint>

#define NNODES 100000
#define D 128
#define EMAX 2000000
#define BN_EPS 1e-5f

// ---------------- device scratch (no dynamic allocation allowed) ----------------
__device__ __half g_hh[(size_t)NNODES * D];   // h = x @ W^T (UNSCALED), fp16 (25.6 MB)
__device__ float g_dinv[NNODES];              // 1/sqrt(deg)
__device__ int   g_counts[NNODES];            // in-degree (excluding self loop)
__device__ int   g_rowstart[NNODES];          // CSR row offsets (LOCAL to scan1 block)
__device__ int   g_cursor[NNODES];            // fill cursors (LOCAL)
__device__ int   g_csr[EMAX];                 // CSR column (src) indices
__device__ int   g_blocksums[128];            // scan1 block sums -> exclusive prefixes
__device__ float g_stats[2 * D];              // sums / sumsq
__device__ int   g_is64;                      // edge_index dtype flag
// W as fp16, stored pre-swizzled (ldmatrix layout), 32KB
__device__ __align__(16) __half g_Wf16_img[16384];

// ---------------- warp-mma helpers (plain sm_80+ PTX, no 'a'-gated features) -----
__device__ __forceinline__ uint32_t smem_u32(const void* p) {
    uint32_t a;
    asm("{ .reg .u64 t; cvta.to.shared.u64 t, %1; cvt.u32.u64 %0, t; }" : "=r"(a) : "l"(p));
    return a;
}
__device__ __forceinline__ void ldm_x4(uint32_t& r0, uint32_t& r1, uint32_t& r2, uint32_t& r3,
                                       uint32_t addr) {
    asm volatile("ldmatrix.sync.aligned.m8n8.x4.shared.b16 {%0,%1,%2,%3}, [%4];"
                 : "=r"(r0), "=r"(r1), "=r"(r2), "=r"(r3) : "r"(addr));
}
__device__ __forceinline__ void mma_f16(float* c, const uint32_t* a, const uint32_t* b) {
    asm volatile(
        "mma.sync.aligned.m16n8k16.row.col.f32.f16.f16.f32 "
        "{%0,%1,%2,%3},{%4,%5,%6,%7},{%8,%9},{%0,%1,%2,%3};"
        : "+f"(c[0]), "+f"(c[1]), "+f"(c[2]), "+f"(c[3])
        : "r"(a[0]), "r"(a[1]), "r"(a[2]), "r"(a[3]), "r"(b[0]), "r"(b[1]));
}
__device__ __forceinline__ void cpasync16(uint32_t dst, const void* src) {
    asm volatile("cp.async.cg.shared.global [%0], [%1], 16;" :: "r"(dst), "l"(src));
}

// ---------------- edge index access (dtype detected at runtime) ----------------
__device__ __forceinline__ int edge_at(const void* ei, long long pos) {
    if (g_is64) return (int)((const long long*)ei)[pos];
    return ((const int*)ei)[pos];
}

// winit: W fp16 image + dtype detect + stats zero (tiny; unblocks GEMM immediately)
__global__ void k_winit(const int* ei32, const float* __restrict__ W, int E) {
    int i = blockIdx.x * blockDim.x + threadIdx.x;
    if (blockIdx.x == 0 && threadIdx.x < 32) {
        // int64 little-endian => odd int32 words of first 64 pairs are all zero
        int lane = threadIdx.x;
        int bad = 0;
        if (lane < E && ei32[2 * lane + 1] != 0) bad = 1;
        int k2 = lane + 32;
        if (k2 < E && k2 < 64 && ei32[2 * k2 + 1] != 0) bad = 1;
        unsigned m = __ballot_sync(0xffffffffu, bad);
        if (lane == 0) g_is64 = (m == 0u);
    }
    if (i < 2 * D) g_stats[i] = 0.0f;
    if (i < 16384) {
        int r = i >> 7, k = i & 127;
        int kc = k >> 3;
        int idx = (r * 16 + (kc ^ (r & 7))) * 8 + (k & 7);
        g_Wf16_img[idx] = __float2half(W[i]);
    }
}

// zero counts
__global__ void k_zero(int N) {
    int i = blockIdx.x * blockDim.x + threadIdx.x;
    if (i < N) g_counts[i] = 0;
}

// hist: 1 edge/thread (proven form)
__global__ void k_hist(const void* ei, int E) {
    int e = blockIdx.x * blockDim.x + threadIdx.x;
    if (e >= E) return;
    int d = edge_at(ei, (long long)E + e);
    atomicAdd(&g_counts[d], 1);
}

// scan1: within-block exclusive scan (LOCAL); writes rowstart+cursor local, dinv, blocksums
__global__ void k_scan1(int N) {
    __shared__ int warp_off[32];
    int t = threadIdx.x;
    int gid = blockIdx.x * 1024 + t;
    int v = (gid < N) ? g_counts[gid] : 0;
    int lane = t & 31, wid = t >> 5;
    int s = v;
#pragma unroll
    for (int off = 1; off < 32; off <<= 1) {
        int n2 = __shfl_up_sync(0xffffffffu, s, off);
        if (lane >= off) s += n2;
    }
    if (lane == 31) warp_off[wid] = s;
    __syncthreads();
    if (wid == 0) {
        int ws = warp_off[lane];
        int ss = ws;
#pragma unroll
        for (int off = 1; off < 32; off <<= 1) {
            int n2 = __shfl_up_sync(0xffffffffu, ss, off);
            if (lane >= off) ss += n2;
        }
        warp_off[lane] = ss - ws;
        if (lane == 31) g_blocksums[blockIdx.x] = ss;
    }
    __syncthreads();
    if (gid < N) {
        int loc = s + warp_off[wid] - v;     // local exclusive
        g_rowstart[gid] = loc;
        g_cursor[gid]   = loc;
        g_dinv[gid]     = rsqrtf((float)v + 1.0f);
    }
}

// scan2: 1 block; blocksums -> exclusive prefixes in place
__global__ void k_scan2(int nblk) {
    __shared__ int sh[128];
    int t = threadIdx.x;
    int v = (t < nblk) ? g_blocksums[t] : 0;
    sh[t] = v;
    __syncthreads();
    for (int off = 1; off < 128; off <<= 1) {
        int add = (t >= off) ? sh[t - off] : 0;
        __syncthreads();
        sh[t] += add;
        __syncthreads();
    }
    if (t < nblk) g_blocksums[t] = sh[t] - v;   // exclusive prefix
}

// fill: global slot = local cursor + block prefix
__global__ void k_fill(const void* ei, int E) {
    int e = blockIdx.x * blockDim.x + threadIdx.x;
    if (e >= E) return;
    int s = edge_at(ei, e);
    int d = edge_at(ei, (long long)E + e);
    int pos = atomicAdd(&g_cursor[d], 1) + g_blocksums[d >> 10];
    if (pos >= 0 && pos < EMAX) g_csr[pos] = s;
}

// ---- GEMM: h = x_f16 @ W_f16^T (UNSCALED) -> fp16; A direct from global --------
#define SM_TOT 32768

__global__ __launch_bounds__(256, 2) void k_gemm_mma(const float* __restrict__ x, int N) {
    extern __shared__ char smem[];
    uint32_t sb = smem_u32(smem);
    int tid = threadIdx.x;
    int row0 = blockIdx.x * 128;

    {
        const char* wsrc = (const char*)g_Wf16_img;
        for (int i = tid; i < 2048; i += 256)
            cpasync16(sb + i * 16, wsrc + i * 16);
        asm volatile("cp.async.commit_group;" ::: "memory");
    }

    int warp = tid >> 5, lane = tid & 31;
    int wm = warp & 3, wn = warp >> 2;
    int m0 = wm * 32, n0 = wn * 64;
    int sub = lane >> 3, lrow = lane & 7;
    int qrow = lane >> 2, c0 = (lane & 3) * 2;

    const float* xptr[2][2];
    int rbase = row0 + m0 + qrow;
#pragma unroll
    for (int mt = 0; mt < 2; mt++) {
        int r0i = rbase + mt * 16;
        int r1i = r0i + 8;
        xptr[mt][0] = x + (size_t)min(r0i, N - 1) * 128;
        xptr[mt][1] = x + (size_t)min(r1i, N - 1) * 128;
    }

    float acc[2][8][4];
#pragma unroll
    for (int mt = 0; mt < 2; mt++)
#pragma unroll
        for (int nt = 0; nt < 8; nt++)
#pragma unroll
            for (int q = 0; q < 4; q++) acc[mt][nt][q] = 0.f;

    int b_row_off = ((sub & 2) << 2) + lrow;
    int b_halfk   = sub & 1;

    asm volatile("cp.async.wait_group 0;" ::: "memory");
    __syncthreads();

#pragma unroll
    for (int ks = 0; ks < 8; ks++) {
        int kb = ks * 16 + c0;
        uint32_t a[2][4];
#pragma unroll
        for (int mt = 0; mt < 2; mt++) {
            float2 f0 = *(const float2*)(xptr[mt][0] + kb);
            float2 f1 = *(const float2*)(xptr[mt][1] + kb);
            float2 f2 = *(const float2*)(xptr[mt][0] + kb + 8);
            float2 f3 = *(const float2*)(xptr[mt][1] + kb + 8);
            __half2 h0 = __floats2half2_rn(f0.x, f0.y);
            __half2 h1 = __floats2half2_rn(f1.x, f1.y);
            __half2 h2 = __floats2half2_rn(f2.x, f2.y);
            __half2 h3 = __floats2half2_rn(f3.x, f3.y);
            a[mt][0] = *(uint32_t*)&h0;
            a[mt][1] = *(uint32_t*)&h1;
            a[mt][2] = *(uint32_t*)&h2;
            a[mt][3] = *(uint32_t*)&h3;
        }
        uint32_t b[8][2];
#pragma unroll
        for (int np = 0; np < 4; np++) {
            int r = n0 + np * 16 + b_row_off;
            int kc = 2 * ks + b_halfk;
            uint32_t addr = (uint32_t)((r * 16 + (kc ^ (r & 7))) * 16);
            ldm_x4(b[2 * np][0], b[2 * np][1], b[2 * np + 1][0], b[2 * np + 1][1],
                   sb + addr);
        }
#pragma unroll
        for (int mt = 0; mt < 2; mt++)
#pragma unroll
            for (int nt = 0; nt < 8; nt++)
                mma_f16(acc[mt][nt], a[mt], b[nt]);
    }

    // ---- epilogue: plain fp16 stores (no scaling) ----
    int qcol = (lane & 3) * 2;
    __half2* h2p = (__half2*)g_hh;
#pragma unroll
    for (int mt = 0; mt < 2; mt++) {
        int r_lo = row0 + m0 + mt * 16 + qrow;
        int r_hi = r_lo + 8;
#pragma unroll
        for (int nt = 0; nt < 8; nt++) {
            int col = n0 + nt * 8 + qcol;
            if (r_lo < N)
                h2p[(size_t)r_lo * 64 + (col >> 1)] =
                    __floats2half2_rn(acc[mt][nt][0], acc[mt][nt][1]);
            if (r_hi < N)
                h2p[(size_t)r_hi * 64 + (col >> 1)] =
                    __floats2half2_rn(acc[mt][nt][2], acc[mt][nt][3]);
        }
    }
}

// ------- aggregation: dinv applied per-edge; + fused BN statistics ---------------
// out[dst] = dinv_dst * ( sum_nbrs dinv_src*h[src] + dinv_dst*h[dst] ) + b
__global__ __launch_bounds__(256) void k_agg(const float* __restrict__ bias,
                                             float* __restrict__ out, int N, int totalWarps) {
    __shared__ float sh_sum[128];
    __shared__ float sh_sq[128];
    int tid = threadIdx.x;
    int lane = tid & 31;
    if (tid < 128) { sh_sum[tid] = 0.f; sh_sq[tid] = 0.f; }
    __syncthreads();

    int gwarp = blockIdx.x * 8 + (tid >> 5);
    const uint2* hrow = (const uint2*)g_hh;   // 32 uint2 per 128-half row
    float4 bb = ((const float4*)bias)[lane];
    float4 ssum = make_float4(0.f, 0.f, 0.f, 0.f);
    float4 ssq  = make_float4(0.f, 0.f, 0.f, 0.f);

    for (int node = gwarp; node < N; node += totalWarps) {
        int   base = g_rowstart[node] + g_blocksums[node >> 10];
        int   cnt  = g_counts[node];
        float di   = g_dinv[node];

        float4 a0, a1, a2, a3;
        {
            uint2 v = hrow[(size_t)node * 32 + lane];
            float2 p0 = __half22float2(*(__half2*)&v.x);
            float2 p1 = __half22float2(*(__half2*)&v.y);
            a0 = make_float4(di * p0.x, di * p0.y, di * p1.x, di * p1.y);  // self: dinv*h
        }
        a1 = make_float4(0.f, 0.f, 0.f, 0.f);
        a2 = make_float4(0.f, 0.f, 0.f, 0.f);
        a3 = make_float4(0.f, 0.f, 0.f, 0.f);

        for (int j0 = 0; j0 < cnt; j0 += 32) {
            int myj = j0 + lane;
            int   s   = 0;
            float mns = 0.f;
            if (myj < cnt) {
                s   = g_csr[base + myj];
                mns = g_dinv[s];
            }
            int m = min(32, cnt - j0);
            int t = 0;
            for (; t + 4 <= m; t += 4) {
                int sv0 = __shfl_sync(0xffffffffu, s, t);
                int sv1 = __shfl_sync(0xffffffffu, s, t + 1);
                int sv2 = __shfl_sync(0xffffffffu, s, t + 2);
                int sv3 = __shfl_sync(0xffffffffu, s, t + 3);
                float n0 = __shfl_sync(0xffffffffu, mns, t);
                float n1 = __shfl_sync(0xffffffffu, mns, t + 1);
                float n2 = __shfl_sync(0xffffffffu, mns, t + 2);
                float n3 = __shfl_sync(0xffffffffu, mns, t + 3);
                uint2 v0 = hrow[(size_t)sv0 * 32 + lane];
                uint2 v1 = hrow[(size_t)sv1 * 32 + lane];
                uint2 v2 = hrow[(size_t)sv2 * 32 + lane];
                uint2 v3 = hrow[(size_t)sv3 * 32 + lane];
                float2 q0, q1;
                q0 = __half22float2(*(__half2*)&v0.x); q1 = __half22float2(*(__half2*)&v0.y);
                a0.x += n0 * q0.x; a0.y += n0 * q0.y; a0.z += n0 * q1.x; a0.w += n0 * q1.y;
                q0 = __half22float2(*(__half2*)&v1.x); q1 = __half22float2(*(__half2*)&v1.y);
                a1.x += n1 * q0.x; a1.y += n1 * q0.y; a1.z += n1 * q1.x; a1.w += n1 * q1.y;
                q0 = __half22float2(*(__half2*)&v2.x); q1 = __half22float2(*(__half2*)&v2.y);
                a2.x += n2 * q0.x; a2.y += n2 * q0.y; a2.z += n2 * q1.x; a2.w += n2 * q1.y;
                q0 = __half22float2(*(__half2*)&v3.x); q1 = __half22float2(*(__half2*)&v3.y);
                a3.x += n3 * q0.x; a3.y += n3 * q0.y; a3.z += n3 * q1.x; a3.w += n3 * q1.y;
            }
            for (; t < m; t++) {
                int   sv0 = __shfl_sync(0xffffffffu, s, t);
                float n0  = __shfl_sync(0xffffffffu, mns, t);
                uint2 v0 = hrow[(size_t)sv0 * 32 + lane];
                float2 q0 = __half22float2(*(__half2*)&v0.x);
                float2 q1 = __half22float2(*(__half2*)&v0.y);
                a0.x += n0 * q0.x; a0.y += n0 * q0.y; a0.z += n0 * q1.x; a0.w += n0 * q1.y;
            }
        }
        float4 o;
        o.x = di * ((a0.x + a1.x) + (a2.x + a3.x)) + bb.x;
        o.y = di * ((a0.y + a1.y) + (a2.y + a3.y)) + bb.y;
        o.z = di * ((a0.z + a1.z) + (a2.z + a3.z)) + bb.z;
        o.w = di * ((a0.w + a1.w) + (a2.w + a3.w)) + bb.w;
        ((float4*)out)[(size_t)node * 32 + lane] = o;
        ssum.x += o.x; ssum.y += o.y; ssum.z += o.z; ssum.w += o.w;
        ssq.x += o.x * o.x; ssq.y += o.y * o.y; ssq.z += o.z * o.z; ssq.w += o.w * o.w;
    }

    atomicAdd(&sh_sum[lane * 4 + 0], ssum.x);
    atomicAdd(&sh_sum[lane * 4 + 1], ssum.y);
    atomicAdd(&sh_sum[lane * 4 + 2], ssum.z);
    atomicAdd(&sh_sum[lane * 4 + 3], ssum.w);
    atomicAdd(&sh_sq[lane * 4 + 0], ssq.x);
    atomicAdd(&sh_sq[lane * 4 + 1], ssq.y);
    atomicAdd(&sh_sq[lane * 4 + 2], ssq.z);
    atomicAdd(&sh_sq[lane * 4 + 3], ssq.w);
    __syncthreads();
    if (tid < 128) {
        atomicAdd(&g_stats[tid], sh_sum[tid]);
        atomicAdd(&g_stats[D + tid], sh_sq[tid]);
    }
}

// ---------------- BN + ReLU + residual -------------------------------------------
__global__ void k_final(const float* __restrict__ x, const float* __restrict__ gamma,
                        const float* __restrict__ beta, float* __restrict__ out, int N) {
    long long i = (long long)blockIdx.x * blockDim.x + threadIdx.x;
    long long total = (long long)N * 32;
    if (i >= total) return;
    int c4 = (int)(i & 31);
    float invN = 1.0f / (float)N;
    float4 v  = ((float4*)out)[i];
    float4 xv = ((const float4*)x)[i];
    float r[4] = {v.x, v.y, v.z, v.w};
    float xr[4] = {xv.x, xv.y, xv.z, xv.w};
#pragma unroll
    for (int c = 0; c < 4; c++) {
        int col = c4 * 4 + c;
        float mu  = g_stats[col] * invN;
        float var = g_stats[D + col] * invN - mu * mu;
        float inv = rsqrtf(var + BN_EPS);
        float y = __ldg(&gamma[col]) * (r[c] - mu) * inv + __ldg(&beta[col]);
        y = fmaxf(y, 0.0f);
        r[c] = y + xr[c];
    }
    ((float4*)out)[i] = make_float4(r[0], r[1], r[2], r[3]);
}

// ---------------- launcher: GEMM forked at the very start ------------------------
extern "C" void kernel_launch(void* const* d_in, const int* in_sizes, int n_in,
                              void* d_out, int out_size) {
    const float* x     = (const float*)d_in[0];
    const float* W     = (const float*)d_in[1];
    const float* bias  = (const float*)d_in[2];
    const float* gamma = (const float*)d_in[3];
    const float* beta  = (const float*)d_in[4];
    const void*  ei    = d_in[5];
    int N = in_sizes[0] / D;
    int E = in_sizes[5] / 2;
    float* out = (float*)d_out;

    cudaFuncSetAttribute(k_gemm_mma, cudaFuncAttributeMaxDynamicSharedMemorySize, SM_TOT);

    cudaStream_t s2;
    cudaStreamCreate(&s2);
    cudaEvent_t evFork, evJoin;
    cudaEventCreateWithFlags(&evFork, cudaEventDisableTiming);
    cudaEventCreateWithFlags(&evJoin, cudaEventDisableTiming);

    int nblk = (N + 1023) / 1024;

    // 1) W image (tiny) -> immediately fork GEMM (depends on nothing else)
    k_winit<<<64, 256>>>((const int*)ei, W, E);
    cudaEventRecord(evFork, 0);
    cudaStreamWaitEvent(s2, evFork, 0);
    k_gemm_mma<<<(N + 127) / 128, 256, SM_TOT, s2>>>(x, N);
    cudaEventRecord(evJoin, s2);

    // 2) CSR chain on main stream (concurrent with GEMM)
    k_zero<<<(N + 255) / 256, 256>>>(N);
    k_hist<<<(E + 255) / 256, 256>>>(ei, E);
    k_scan1<<<nblk, 1024>>>(N);
    k_scan2<<<1, 128>>>(nblk);
    k_fill<<<(E + 255) / 256, 256>>>(ei, E);

    // 3) join, aggregate, finalize
    cudaStreamWaitEvent(0, evJoin, 0);
    int aggBlocks = 1036;
    k_agg<<<aggBlocks, 256>>>(bias, out, N, aggBlocks * 8);
    k_final<<<(int)(((long long)N * 32 + 255) / 256), 256>>>(x, gamma, beta, out, N);

    cudaEventDestroy(evFork);
    cudaEventDestroy(evJoin);
    cudaStreamDestroy(s2);
}